// round 11
// baseline (speedup 1.0000x reference)
#include <cuda_runtime.h>
#include <cuda_bf16.h>

// ArcSoftmaxLoss: loss = mean_b [ logsumexp_j(64*costh) - target_b ],
// label column replaced by 64*cos(acos(c_y)+0.5).
//
// Fixed-max LSE (M = 63.36 >= all logits since |costh| < 0.99).
// Flat-range decomposition, R4 memory shape restored:
//   - GRID=444 (148 SMs x 3 CTAs), 512-thr blocks -> 48 warps/SM resident
//   - QCHUNK=28832 float4 (multiple of 8) -> every chunk start 128B-aligned,
//     so each warp LDG.128 touches exactly 4 cache lines (flat chunks in
//     R6/R8 were misaligned -> 5 lines/warp -> +25% L1tex wavefronts)
// Per-row partials via atomicAdd; ticket counter elects the last block per
// row to do label fix-up + log + mean (no 2nd kernel). Self-cleaning state.
//
// exp via clamp-free 2^(x/2) degree-4 poly squared into the accumulator:
// 10 FMA/ALU ops per element, ~8e-5 rel err per term (tolerance 1e-3).

#define BATCH  512
#define NCLS   100000
#define NVEC   (NCLS / 4)            // 25000 float4 per row (400000B, 128B-aligned)
#define TOT4   (BATCH * NVEC)        // 12,800,000 float4 total
#define GRID   444                   // 148 SMs * 3 CTAs
#define NTHR   512
#define QCHUNK 28832                 // ceil(TOT4/444) rounded to mult of 8

#define LOG2E 1.4426950408889634f
#define MMAX  63.36f                 // 64 * 0.99
#define K1H   (0.5f * 64.0f * LOG2E)
#define K2H   (0.5f * -MMAX * LOG2E)
#define COS_M 0.8775825618903728f    // cos(0.5)
#define SIN_M 0.47942553860420300f   // sin(0.5)

__device__ float    g_rowsum[BATCH];   // zero-init; finisher re-zeroes
__device__ unsigned g_count[BATCH];    // zero-init; finisher re-zeroes

// acc += exp(64*c - MMAX), via (2^((64c-M)*log2e/2))^2. No clamps.
__device__ __forceinline__ float expacc(float c, float acc) {
    float y = fmaf(c, K1H, K2H);                  // in [-91.4, 0]
    float r = y + 12582912.0f;                    // 1.5*2^23 round-to-int
    float f = y - (r - 12582912.0f);              // frac in [-0.5, 0.5]
    float p = fmaf(9.61844e-3f, f, 5.550411e-2f); // deg-4 2^f
    p = fmaf(p, f, 2.4022651e-1f);
    p = fmaf(p, f, 6.9314718e-1f);
    p = fmaf(p, f, 1.0f);
    // m<<23 == bits(r)<<23 (magic constant's low 9 bits are zero)
    float eh = __int_as_float(__float_as_int(p) + (__float_as_int(r) << 23));
    return fmaf(eh, eh, acc);
}

__device__ __forceinline__ float expv(float c) { return expacc(c, 0.0f); }

__global__ __launch_bounds__(NTHR)
void arc_flat_kernel(const float* __restrict__ costh,
                     const int* __restrict__ label,
                     float* __restrict__ out) {
    const int tid = threadIdx.x;
    int s = blockIdx.x * QCHUNK;
    const int e = min(s + QCHUNK, TOT4);
    const float4* base4 = reinterpret_cast<const float4*>(costh);

    __shared__ float ws[NTHR / 32];

    while (s < e) {
        const int row     = s / NVEC;
        const int seg_end = min(e, (row + 1) * NVEC);

        // Prefetch the label gather so the (possible) finisher never stalls.
        float cy = 0.0f;
        if (tid == 0) {
            int lab = label[row];
            lab = max(0, min(lab, NCLS - 1));
            cy = __ldg(costh + (size_t)row * NCLS + lab);
        }

        // Streaming partial sum over [s, seg_end): 128B-aligned, coalesced.
        float s0 = 0.f, s1 = 0.f, s2 = 0.f, s3 = 0.f;
        #pragma unroll 4
        for (int v = s + tid; v < seg_end; v += NTHR) {
            float4 c = base4[v];
            s0 = expacc(c.x, s0);
            s1 = expacc(c.y, s1);
            s2 = expacc(c.z, s2);
            s3 = expacc(c.w, s3);
        }
        float part = (s0 + s1) + (s2 + s3);

        #pragma unroll
        for (int o = 16; o > 0; o >>= 1)
            part += __shfl_xor_sync(0xFFFFFFFFu, part, o);
        if ((tid & 31) == 0) ws[tid >> 5] = part;
        __syncthreads();

        if (tid == 0) {
            float blocksum = 0.f;
            #pragma unroll
            for (int i = 0; i < NTHR / 32; i++) blocksum += ws[i];

            atomicAdd(&g_rowsum[row], blocksum);
            __threadfence();                       // release rowsum before ticket
            unsigned old = atomicAdd(&g_count[row], 1u);

            // Number of blocks overlapping this row (contiguous Q-chunks).
            const int first = (row * NVEC) / QCHUNK;
            const int last  = ((row + 1) * NVEC - 1) / QCHUNK;
            const unsigned expected = (unsigned)(last - first + 1);

            if (old == expected - 1u) {            // last block for this row
                __threadfence();                   // acquire rowsum
                float tot = *((volatile float*)&g_rowsum[row]);

                // Replace the target column's contribution.
                float sn  = sqrtf(fmaxf(1.0f - cy * cy, 0.0f));
                float cym = cy * COS_M - sn * SIN_M;  // cos(acos(cy)+0.5)
                tot = tot - expv(cy) + expv(cym);

                float loss = (MMAX + logf(tot)) - 64.0f * cym;
                atomicAdd(out, loss * (1.0f / BATCH));

                // Self-clean for the next graph replay.
                g_count[row]  = 0u;
                *((volatile float*)&g_rowsum[row]) = 0.0f;
            }
        }
        __syncthreads();                           // ws reuse across segments
        s = seg_end;
    }
}

extern "C" void kernel_launch(void* const* d_in, const int* in_sizes, int n_in,
                              void* d_out, int out_size) {
    const float* costh = (const float*)d_in[0];
    const int*   label = (const int*)d_in[1];
    float* out = (float*)d_out;

    cudaMemsetAsync(out, 0, sizeof(float));
    arc_flat_kernel<<<GRID, NTHR>>>(costh, label, out);
}

// round 16
// speedup vs baseline: 1.2433x; 1.2433x over previous
#include <cuda_runtime.h>
#include <cuda_bf16.h>

// ArcSoftmaxLoss: loss = mean_b [ logsumexp_j(64*costh) - target_b ],
// label column replaced by 64*cos(acos(c_y)+0.5).
//
// Fixed-max LSE (M = 63.36 >= all logits since |costh| < 0.99).
// Half-row decomposition with COMPILE-TIME loop bounds (the one property all
// fast rounds shared and all slow flat rounds lacked — static trip counts let
// ptxas front-batch the LDG.128 stream):
//   grid = 1024 (= 2 blocks/row), 512 threads; block handles 12500 float4.
//   Balance ~1.01 (vs R4's 1.16 with 512 blocks on 148 SMs).
// Both half-blocks atomicAdd into g_rowsum[row]; ticket counter (expected=2)
// elects the last to do the label fix-up + log + mean contribution. State
// self-cleans for graph replays; out zeroed by a memset node.
//
// exp via clamp-free 2^(x/2) degree-4 poly squared into the accumulator:
// 10 FMA/ALU ops per element, ~8e-5 rel err per term (tolerance 1e-3).

#define BATCH  512
#define NCLS   100000
#define HALF   (NCLS / 2)            // 50000 elements per half-row
#define HALF4  (HALF / 4)            // 12500 float4, compile-time trip count
#define GRID   (2 * BATCH)           // 1024 blocks
#define NTHR   512

#define LOG2E 1.4426950408889634f
#define MMAX  63.36f                 // 64 * 0.99
#define K1H   (0.5f * 64.0f * LOG2E)
#define K2H   (0.5f * -MMAX * LOG2E)
#define COS_M 0.8775825618903728f    // cos(0.5)
#define SIN_M 0.47942553860420300f   // sin(0.5)

__device__ float    g_rowsum[BATCH];   // zero-init; finisher re-zeroes
__device__ unsigned g_count[BATCH];    // zero-init; finisher re-zeroes

// acc += exp(64*c - MMAX), via (2^((64c-M)*log2e/2))^2. No clamps:
// half-exponent keeps the bit reconstruction from wrapping (y in [-91.4, 0]);
// the square underflows gracefully for negligible terms.
__device__ __forceinline__ float expacc(float c, float acc) {
    float y = fmaf(c, K1H, K2H);
    float r = y + 12582912.0f;                    // 1.5*2^23 round-to-int
    float f = y - (r - 12582912.0f);              // frac in [-0.5, 0.5]
    float p = fmaf(9.61844e-3f, f, 5.550411e-2f); // deg-4 2^f
    p = fmaf(p, f, 2.4022651e-1f);
    p = fmaf(p, f, 6.9314718e-1f);
    p = fmaf(p, f, 1.0f);
    // m<<23 == bits(r)<<23 (magic constant's low 9 bits are zero)
    float eh = __int_as_float(__float_as_int(p) + (__float_as_int(r) << 23));
    return fmaf(eh, eh, acc);
}

__device__ __forceinline__ float expv(float c) { return expacc(c, 0.0f); }

__global__ __launch_bounds__(NTHR)
void arc_half_kernel(const float* __restrict__ costh,
                     const int* __restrict__ label,
                     float* __restrict__ out) {
    const int tid  = threadIdx.x;
    const int row  = blockIdx.x >> 1;
    const int half = blockIdx.x & 1;
    const float* rowp = costh + (size_t)row * NCLS;
    const float4* p4 = reinterpret_cast<const float4*>(rowp + half * HALF);

    // Prefetch the label gather so the (possible) finisher never stalls.
    float cy = 0.0f;
    if (tid == 0) {
        int lab = label[row];
        lab = max(0, min(lab, NCLS - 1));
        cy = __ldg(rowp + lab);
    }

    // Streaming partial sum: STATIC trip count (HALF4 / NTHR).
    float s0 = 0.f, s1 = 0.f, s2 = 0.f, s3 = 0.f;
    #pragma unroll 4
    for (int i = tid; i < HALF4; i += NTHR) {
        float4 c = p4[i];
        s0 = expacc(c.x, s0);
        s1 = expacc(c.y, s1);
        s2 = expacc(c.z, s2);
        s3 = expacc(c.w, s3);
    }
    float part = (s0 + s1) + (s2 + s3);

    #pragma unroll
    for (int o = 16; o > 0; o >>= 1)
        part += __shfl_xor_sync(0xFFFFFFFFu, part, o);

    __shared__ float ws[NTHR / 32];
    if ((tid & 31) == 0) ws[tid >> 5] = part;
    __syncthreads();

    if (tid == 0) {
        float blocksum = 0.f;
        #pragma unroll
        for (int i = 0; i < NTHR / 32; i++) blocksum += ws[i];

        atomicAdd(&g_rowsum[row], blocksum);
        __threadfence();                       // release rowsum before ticket
        unsigned old = atomicAdd(&g_count[row], 1u);

        if (old == 1u) {                       // second (last) half for this row
            __threadfence();                   // acquire rowsum
            float tot = *((volatile float*)&g_rowsum[row]);

            // Replace the target column's contribution.
            float sn  = sqrtf(fmaxf(1.0f - cy * cy, 0.0f));
            float cym = cy * COS_M - sn * SIN_M;  // cos(acos(cy)+0.5)
            tot = tot - expv(cy) + expv(cym);

            float loss = (MMAX + logf(tot)) - 64.0f * cym;
            atomicAdd(out, loss * (1.0f / BATCH));

            // Self-clean for the next graph replay.
            g_count[row] = 0u;
            *((volatile float*)&g_rowsum[row]) = 0.0f;
        }
    }
}

extern "C" void kernel_launch(void* const* d_in, const int* in_sizes, int n_in,
                              void* d_out, int out_size) {
    const float* costh = (const float*)d_in[0];
    const int*   label = (const int*)d_in[1];
    float* out = (float*)d_out;

    cudaMemsetAsync(out, 0, sizeof(float));
    arc_half_kernel<<<GRID, NTHR>>>(costh, label, out);
}

// round 17
// speedup vs baseline: 1.3191x; 1.0610x over previous
#include <cuda_runtime.h>
#include <cuda_bf16.h>

// ArcSoftmaxLoss: loss = mean_b [ logsumexp_j(64*costh) - target_b ],
// label column replaced by 64*cos(acos(c_y)+0.5).
//
// Fixed-max LSE (M = 63.36 >= all logits since |costh| < 0.99).
// Half-row decomposition, compile-time loop bounds, fused ticket finisher
// (unchanged from R10). THE change this round: exp via MUFU ex2.approx —
//   acc += ex2(fmaf(c, 64*log2e, -M*log2e))
// 3 warp-ops/element vs the 10-op polynomial. MUFU sustains 16 elem/cyc/SM
// (rt_SMSP=8, 32 lanes) = 2x the 8 TB/s DRAM feed rate; issue drops from
// ~45% to ~24%. ftz flushes the far tail (x ~ -183) to zero: no clamps.
// ex2 ulp error ~1.16|x| -> dominant terms (x in [-5,0]) ~1e-6 rel.

#define BATCH  512
#define NCLS   100000
#define HALF   (NCLS / 2)            // 50000 elements per half-row
#define HALF4  (HALF / 4)            // 12500 float4, compile-time trip count
#define GRID   (2 * BATCH)           // 1024 blocks
#define NTHR   512

#define LOG2E 1.4426950408889634f
#define MMAX  63.36f                 // 64 * 0.99
#define K1    (64.0f * LOG2E)        // 92.33248
#define K2    (-MMAX * LOG2E)        // -91.40916
#define COS_M 0.8775825618903728f    // cos(0.5)
#define SIN_M 0.47942553860420300f   // sin(0.5)

__device__ float    g_rowsum[BATCH];   // zero-init; finisher re-zeroes
__device__ unsigned g_count[BATCH];    // zero-init; finisher re-zeroes

__device__ __forceinline__ float ex2a(float x) {
    float r;
    asm("ex2.approx.ftz.f32 %0, %1;" : "=f"(r) : "f"(x));
    return r;
}

// exp(64*c - MMAX) = 2^(c*K1 + K2); input in [-182.8, 0], ftz -> tail = 0.
__device__ __forceinline__ float expv(float c) {
    return ex2a(fmaf(c, K1, K2));
}

__global__ __launch_bounds__(NTHR)
void arc_half_kernel(const float* __restrict__ costh,
                     const int* __restrict__ label,
                     float* __restrict__ out) {
    const int tid  = threadIdx.x;
    const int row  = blockIdx.x >> 1;
    const int half = blockIdx.x & 1;
    const float* rowp = costh + (size_t)row * NCLS;
    const float4* p4 = reinterpret_cast<const float4*>(rowp + half * HALF);

    // Prefetch the label gather so the (possible) finisher never stalls.
    float cy = 0.0f;
    if (tid == 0) {
        int lab = label[row];
        lab = max(0, min(lab, NCLS - 1));
        cy = __ldg(rowp + lab);
    }

    // Streaming partial sum: STATIC trip count, 3 ops/element via MUFU.
    float s0 = 0.f, s1 = 0.f, s2 = 0.f, s3 = 0.f;
    #pragma unroll 4
    for (int i = tid; i < HALF4; i += NTHR) {
        float4 c = p4[i];
        s0 += expv(c.x);
        s1 += expv(c.y);
        s2 += expv(c.z);
        s3 += expv(c.w);
    }
    float part = (s0 + s1) + (s2 + s3);

    #pragma unroll
    for (int o = 16; o > 0; o >>= 1)
        part += __shfl_xor_sync(0xFFFFFFFFu, part, o);

    __shared__ float ws[NTHR / 32];
    if ((tid & 31) == 0) ws[tid >> 5] = part;
    __syncthreads();

    if (tid == 0) {
        float blocksum = 0.f;
        #pragma unroll
        for (int i = 0; i < NTHR / 32; i++) blocksum += ws[i];

        atomicAdd(&g_rowsum[row], blocksum);
        __threadfence();                       // release rowsum before ticket
        unsigned old = atomicAdd(&g_count[row], 1u);

        if (old == 1u) {                       // second (last) half for this row
            __threadfence();                   // acquire rowsum
            float tot = *((volatile float*)&g_rowsum[row]);

            // Replace the target column's contribution.
            float sn  = sqrtf(fmaxf(1.0f - cy * cy, 0.0f));
            float cym = cy * COS_M - sn * SIN_M;  // cos(acos(cy)+0.5)
            tot = tot - expv(cy) + expv(cym);

            float loss = (MMAX + logf(tot)) - 64.0f * cym;
            atomicAdd(out, loss * (1.0f / BATCH));

            // Self-clean for the next graph replay.
            g_count[row] = 0u;
            *((volatile float*)&g_rowsum[row]) = 0.0f;
        }
    }
}

extern "C" void kernel_launch(void* const* d_in, const int* in_sizes, int n_in,
                              void* d_out, int out_size) {
    const float* costh = (const float*)d_in[0];
    const int*   label = (const int*)d_in[1];
    float* out = (float*)d_out;

    cudaMemsetAsync(out, 0, sizeof(float));
    arc_half_kernel<<<GRID, NTHR>>>(costh, label, out);
}